// round 1
// baseline (speedup 1.0000x reference)
#include <cuda_runtime.h>
#include <cstddef>

#define Bq   2
#define Sq   2048
#define HIDD 2048
#define NH   32
#define NKV  8
#define HD   64
#define QKVW ((NH + 2 * NKV) * HD)   /* 3072 */
#define GROUP (NH / NKV)             /* 4 */
#define SCALE 0.125f                 /* HD^-0.5 */

// Scratch (allocation-free rule: device globals)
__device__ float g_qkv [ (size_t)Bq * Sq * QKVW ];      // 12.58M floats
__device__ float g_attn[ (size_t)Bq * Sq * NH * HD ];   // 8.39M floats

// ---------------------------------------------------------------------------
// Classic 128x128x8 SGEMM, 256 threads, 8x8 per-thread accumulator.
// A: MxK row-major, B: KxN row-major, C: MxN row-major. Dims divisible by tile.
// ---------------------------------------------------------------------------
__global__ __launch_bounds__(256) void sgemm128(
    int M, int N, int K,
    const float* __restrict__ A,
    const float* __restrict__ B,
    float* __restrict__ C)
{
    const int BM = 128, BN = 128, BK = 8;
    __shared__ float As[BK][BM];
    __shared__ float Bs[BK][BN];

    int tid  = threadIdx.x;
    int row0 = blockIdx.y * BM;
    int col0 = blockIdx.x * BN;
    int tr = tid / 16;        // 0..15
    int tc = tid % 16;        // 0..15

    // loader indices
    int arow = tid / 2;            // 0..127
    int acol = (tid % 2) * 4;      // 0 or 4
    int brow = tid / 32;           // 0..7
    int bcol = (tid % 32) * 4;     // 0..124

    float acc[8][8];
    #pragma unroll
    for (int i = 0; i < 8; i++)
        #pragma unroll
        for (int j = 0; j < 8; j++) acc[i][j] = 0.f;

    for (int k0 = 0; k0 < K; k0 += BK) {
        float4 a = *(const float4*)(A + (size_t)(row0 + arow) * K + k0 + acol);
        As[acol + 0][arow] = a.x;
        As[acol + 1][arow] = a.y;
        As[acol + 2][arow] = a.z;
        As[acol + 3][arow] = a.w;
        float4 b = *(const float4*)(B + (size_t)(k0 + brow) * N + col0 + bcol);
        *(float4*)&Bs[brow][bcol] = b;
        __syncthreads();

        #pragma unroll
        for (int k = 0; k < BK; k++) {
            float ra[8], rb[8];
            #pragma unroll
            for (int i = 0; i < 8; i++) ra[i] = As[k][tr * 8 + i];
            #pragma unroll
            for (int j = 0; j < 8; j++) rb[j] = Bs[k][tc * 8 + j];
            #pragma unroll
            for (int i = 0; i < 8; i++)
                #pragma unroll
                for (int j = 0; j < 8; j++)
                    acc[i][j] += ra[i] * rb[j];
        }
        __syncthreads();
    }

    #pragma unroll
    for (int i = 0; i < 8; i++) {
        #pragma unroll
        for (int j = 0; j < 8; j += 4) {
            float4 v = make_float4(acc[i][j], acc[i][j+1], acc[i][j+2], acc[i][j+3]);
            *(float4*)(C + (size_t)(row0 + tr * 8 + i) * N + col0 + tc * 8 + j) = v;
        }
    }
}

// ---------------------------------------------------------------------------
// RoPE in-place on the q (NH heads) and k (NKV heads) slices of g_qkv.
// One thread per (token, head, freq-pair).
// ---------------------------------------------------------------------------
__global__ void rope_kernel(const int* __restrict__ positions)
{
    const int total = Bq * Sq * (NH + NKV) * (HD / 2);
    int idx = blockIdx.x * blockDim.x + threadIdx.x;
    if (idx >= total) return;

    int i  = idx & (HD / 2 - 1);                   // freq index 0..31
    int hh = (idx >> 5) % (NH + NKV);              // head (q heads then k heads)
    int bs = idx / ((HD / 2) * (NH + NKV));        // flattened (b, s)

    float pos = (float)positions[bs];
    // inv_freq = 10000^(-(2i)/HD)
    float inv = __expf(-((float)(2 * i) / (float)HD) * 9.210340371976184f);
    float f = pos * inv;
    float c = cosf(f), s = sinf(f);

    float* p = g_qkv + (size_t)bs * QKVW + hh * HD;
    float x1 = p[i];
    float x2 = p[i + HD / 2];
    p[i]          = x1 * c - x2 * s;
    p[i + HD / 2] = x2 * c + x1 * s;
}

// ---------------------------------------------------------------------------
// Causal GQA flash attention. Grid: (Sq/64, NH, Bq), 64 threads/block.
// Each thread owns one q-row: q[64] + acc[64] in registers, online softmax.
// K/V tiles (64x64 each) staged in shared memory.
// ---------------------------------------------------------------------------
__global__ __launch_bounds__(64) void attn_kernel()
{
    int qt  = blockIdx.x;                  // q tile index 0..31
    int h   = blockIdx.y;                  // 0..31
    int b   = blockIdx.z;                  // 0..1
    int hk  = h / GROUP;                   // kv head
    int tid = threadIdx.x;
    int q_idx = qt * 64 + tid;

    __shared__ float Ks[64 * 64];
    __shared__ float Vs[64 * 64];

    const float* qp = g_qkv + ((size_t)(b * Sq + q_idx)) * QKVW + h * HD;
    float q[HD];
    #pragma unroll
    for (int d = 0; d < HD; d++) q[d] = qp[d] * SCALE;

    float m = -1e30f, l = 0.f;
    float acc[HD];
    #pragma unroll
    for (int d = 0; d < HD; d++) acc[d] = 0.f;

    const size_t kbase = (size_t)b * Sq * QKVW + (size_t)NH * HD + (size_t)hk * HD;
    const size_t vbase = (size_t)b * Sq * QKVW + (size_t)(NH + NKV) * HD + (size_t)hk * HD;

    for (int kb = 0; kb <= qt; kb++) {
        __syncthreads();
        // cooperative tile load: 64 threads, coalesced
        for (int i = tid; i < 64 * 64; i += 64) {
            int j = i >> 6;
            int d = i & 63;
            size_t roff = (size_t)(kb * 64 + j) * QKVW + d;
            Ks[i] = g_qkv[kbase + roff];
            Vs[i] = g_qkv[vbase + roff];
        }
        __syncthreads();

        int jmax = (kb == qt) ? (tid + 1) : 64;   // causal mask on diagonal tile
        for (int j = 0; j < jmax; j++) {
            const float* kr = &Ks[j * 64];
            float s = 0.f;
            #pragma unroll
            for (int d = 0; d < HD; d++) s += q[d] * kr[d];

            if (s > m) {   // lazy rescale (rare after warm-up)
                float corr = __expf(m - s);
                l *= corr;
                #pragma unroll
                for (int d = 0; d < HD; d++) acc[d] *= corr;
                m = s;
            }
            float p = __expf(s - m);
            l += p;
            const float* vr = &Vs[j * 64];
            #pragma unroll
            for (int d = 0; d < HD; d++) acc[d] += p * vr[d];
        }
    }

    float invl = 1.f / l;
    float* op = g_attn + ((size_t)(b * Sq + q_idx)) * (NH * HD) + h * HD;
    #pragma unroll
    for (int d = 0; d < HD; d++) op[d] = acc[d] * invl;
}

// ---------------------------------------------------------------------------
// Launch: GEMM1 -> RoPE -> attention -> GEMM2. All on default stream,
// graph-capturable (kernel launches only).
// ---------------------------------------------------------------------------
extern "C" void kernel_launch(void* const* d_in, const int* in_sizes, int n_in,
                              void* d_out, int out_size)
{
    const int*   positions = (const int*)d_in[0];
    const float* hidden    = (const float*)d_in[1];
    const float* Wqkv      = (const float*)d_in[2];
    const float* Wo        = (const float*)d_in[3];
    float*       out       = (float*)d_out;

    float *qkv, *attn;
    cudaGetSymbolAddress((void**)&qkv,  g_qkv);
    cudaGetSymbolAddress((void**)&attn, g_attn);

    // QKV projection: [4096, 2048] @ [2048, 3072]
    {
        dim3 grid(QKVW / 128, (Bq * Sq) / 128);
        sgemm128<<<grid, 256>>>(Bq * Sq, QKVW, HIDD, hidden, Wqkv, qkv);
    }

    // RoPE on q + k slices
    {
        int total = Bq * Sq * (NH + NKV) * (HD / 2);
        rope_kernel<<<(total + 255) / 256, 256>>>(positions);
    }

    // Causal GQA attention
    {
        dim3 grid(Sq / 64, NH, Bq);
        attn_kernel<<<grid, 64>>>();
    }

    // Output projection: [4096, 2048] @ [2048, 2048]
    {
        dim3 grid(HIDD / 128, (Bq * Sq) / 128);
        sgemm128<<<grid, 256>>>(Bq * Sq, HIDD, NH * HD, attn, Wo, out);
    }
}

// round 3
// speedup vs baseline: 1.4733x; 1.4733x over previous
#include <cuda_runtime.h>
#include <cuda_bf16.h>
#include <cstdint>
#include <cstddef>

#define Bq   2
#define Sq   2048
#define HIDD 2048
#define NH   32
#define NKV  8
#define HD   64
#define QKVW ((NH + 2 * NKV) * HD)   /* 3072 */
#define GROUP (NH / NKV)             /* 4 */
#define SCALE 0.125f

#define MROWS   (Bq * Sq)            /* 4096 */
#define N_HID   (NH * HD)            /* 2048 */

// ---------------------------------------------------------------------------
// Scratch (device globals; allocation-free rule)
// ---------------------------------------------------------------------------
__device__ float g_qkv [(size_t)Bq * Sq * QKVW];
__device__ float g_attn[(size_t)Bq * Sq * N_HID];

__device__ __nv_bfloat16 g_hid_hi [(size_t)MROWS * HIDD];
__device__ __nv_bfloat16 g_hid_lo [(size_t)MROWS * HIDD];
__device__ __nv_bfloat16 g_wqkvT_hi[(size_t)QKVW * HIDD];   // [N=3072, K=2048]
__device__ __nv_bfloat16 g_wqkvT_lo[(size_t)QKVW * HIDD];
__device__ __nv_bfloat16 g_woT_hi [(size_t)HIDD * N_HID];   // [N=2048, K=2048]
__device__ __nv_bfloat16 g_woT_lo [(size_t)HIDD * N_HID];
__device__ __nv_bfloat16 g_attn_hi[(size_t)MROWS * N_HID];
__device__ __nv_bfloat16 g_attn_lo[(size_t)MROWS * N_HID];

// ---------------------------------------------------------------------------
// fp32 -> bf16 hi/lo split
// ---------------------------------------------------------------------------
__global__ void convert_split(const float* __restrict__ x,
                              __nv_bfloat16* __restrict__ hi,
                              __nv_bfloat16* __restrict__ lo, int n4)
{
    int i = blockIdx.x * blockDim.x + threadIdx.x;
    if (i >= n4) return;
    float4 v = ((const float4*)x)[i];
    __nv_bfloat16 h0 = __float2bfloat16(v.x);
    __nv_bfloat16 h1 = __float2bfloat16(v.y);
    __nv_bfloat16 h2 = __float2bfloat16(v.z);
    __nv_bfloat16 h3 = __float2bfloat16(v.w);
    __nv_bfloat16 l0 = __float2bfloat16(v.x - __bfloat162float(h0));
    __nv_bfloat16 l1 = __float2bfloat16(v.y - __bfloat162float(h1));
    __nv_bfloat16 l2 = __float2bfloat16(v.z - __bfloat162float(h2));
    __nv_bfloat16 l3 = __float2bfloat16(v.w - __bfloat162float(h3));
    ushort4 hh = make_ushort4(__bfloat16_as_ushort(h0), __bfloat16_as_ushort(h1),
                              __bfloat16_as_ushort(h2), __bfloat16_as_ushort(h3));
    ushort4 ll = make_ushort4(__bfloat16_as_ushort(l0), __bfloat16_as_ushort(l1),
                              __bfloat16_as_ushort(l2), __bfloat16_as_ushort(l3));
    ((ushort4*)hi)[i] = hh;
    ((ushort4*)lo)[i] = ll;
}

// ---------------------------------------------------------------------------
// Transpose fp32 B[R x C] -> bf16 hi/lo [C x R]
// ---------------------------------------------------------------------------
__global__ void transpose_split(const float* __restrict__ B,
                                __nv_bfloat16* __restrict__ Thi,
                                __nv_bfloat16* __restrict__ Tlo, int R, int C)
{
    __shared__ float t[32][33];
    int x = blockIdx.x * 32 + threadIdx.x;
    int y = blockIdx.y * 32 + threadIdx.y;
    #pragma unroll
    for (int j = 0; j < 32; j += 8)
        t[threadIdx.y + j][threadIdx.x] = B[(size_t)(y + j) * C + x];
    __syncthreads();
    int ox = blockIdx.y * 32 + threadIdx.x;
    int oy = blockIdx.x * 32 + threadIdx.y;
    #pragma unroll
    for (int j = 0; j < 32; j += 8) {
        float v = t[threadIdx.x][threadIdx.y + j];
        __nv_bfloat16 h = __float2bfloat16(v);
        Thi[(size_t)(oy + j) * R + ox] = h;
        Tlo[(size_t)(oy + j) * R + ox] = __float2bfloat16(v - __bfloat162float(h));
    }
}

// ---------------------------------------------------------------------------
// mma.sync helpers
// ---------------------------------------------------------------------------
__device__ __forceinline__ uint32_t smem_u32(const void* p) {
    uint32_t a;
    asm("{ .reg .u64 t; cvta.to.shared.u64 t, %1; cvt.u32.u64 %0, t; }"
        : "=r"(a) : "l"(p));
    return a;
}

#define MMA_BF16(c, a, br0, br1) \
    asm volatile("mma.sync.aligned.m16n8k16.row.col.f32.bf16.bf16.f32 " \
        "{%0,%1,%2,%3}, {%4,%5,%6,%7}, {%8,%9}, {%0,%1,%2,%3};" \
        : "+f"((c)[0]), "+f"((c)[1]), "+f"((c)[2]), "+f"((c)[3]) \
        : "r"((a)[0]), "r"((a)[1]), "r"((a)[2]), "r"((a)[3]), "r"(br0), "r"(br1))

#define LDMATRIX_X4(r, addr) \
    asm volatile("ldmatrix.sync.aligned.m8n8.x4.shared.b16 {%0,%1,%2,%3}, [%4];" \
        : "=r"((r)[0]), "=r"((r)[1]), "=r"((r)[2]), "=r"((r)[3]) : "r"(addr))

#define CP_ASYNC16(saddr, gptr) \
    asm volatile("cp.async.cg.shared.global [%0], [%1], 16;" \
        :: "r"(saddr), "l"(gptr))
#define CP_COMMIT() asm volatile("cp.async.commit_group;" ::: "memory")
template <int N> __device__ __forceinline__ void cp_wait() {
    asm volatile("cp.async.wait_group %0;" :: "n"(N) : "memory");
}

// ---------------------------------------------------------------------------
// bf16 3-product GEMM via mma.sync. C[M,N] = A[M,K] * B^T (B stored [N,K]).
// CTA 128x128, 8 warps (warp tile 32x64), K-chunk 32, cp.async double buffer.
// Row pitch 80B in smem -> conflict-free ldmatrix.
// ---------------------------------------------------------------------------
#define ROWB       80            /* padded row bytes (32 bf16 data + 16B pad) */
#define TILEB      (128 * ROWB)  /* 10240 */
#define STAGEB     (4 * TILEB)   /* 40960: Ahi, Alo, Bhi, Blo */
#define GEMM_SMEM  (2 * STAGEB)  /* 81920 */

__global__ __launch_bounds__(256, 1) void gemm_mma(
    int M, int N, int K,
    const __nv_bfloat16* __restrict__ Ahi, const __nv_bfloat16* __restrict__ Alo,
    const __nv_bfloat16* __restrict__ Bhi, const __nv_bfloat16* __restrict__ Blo,
    float* __restrict__ C)
{
    extern __shared__ char smem[];
    const uint32_t sbase = smem_u32(smem);
    const int tid  = threadIdx.x;
    const int wid  = tid >> 5;
    const int lane = tid & 31;
    const int m0 = blockIdx.y * 128;
    const int n0 = blockIdx.x * 128;
    const int wm = (wid >> 1) * 32;      // warp m offset 0..96
    const int wn = (wid & 1) * 64;       // warp n offset 0/64

    const __nv_bfloat16* srcs[4] = {
        Ahi + (size_t)m0 * K, Alo + (size_t)m0 * K,
        Bhi + (size_t)n0 * K, Blo + (size_t)n0 * K
    };

    // ldmatrix per-lane address components
    const int q  = lane >> 3;    // quadrant 0..3
    const int ri = lane & 7;     // row in quadrant
    // A: row = r0 + (q&1)*8 + ri, col = kk + (q>>1)*8
    const int a_row_add = ((q & 1) << 3) + ri;
    const int a_col_add = (q >> 1) << 3;
    // B: row = n_r0 + (q>>1)*8 + ri, col = kk + (q&1)*8
    const int b_row_add = ((q >> 1) << 3) + ri;
    const int b_col_add = (q & 1) << 3;

    float acc[2][8][4];
    #pragma unroll
    for (int mi = 0; mi < 2; mi++)
        #pragma unroll
        for (int ni = 0; ni < 8; ni++)
            #pragma unroll
            for (int c = 0; c < 4; c++) acc[mi][ni][c] = 0.f;

    const int NC = K >> 5;   // chunks of 32

    // chunk loader: 4 tiles x 128 rows x 64B (4x16B), into padded 80B rows
    auto load_chunk = [&](int stage, int k0) {
        uint32_t sdst = sbase + stage * STAGEB;
        #pragma unroll
        for (int t = 0; t < 4; t++) {
            #pragma unroll
            for (int u = 0; u < 2; u++) {
                int idx = tid + u * 256;        // 0..511
                int row = idx >> 2;
                int seg = idx & 3;
                const __nv_bfloat16* g = srcs[t] + (size_t)row * K + k0 + seg * 8;
                CP_ASYNC16(sdst + t * TILEB + row * ROWB + seg * 16, g);
            }
        }
        CP_COMMIT();
    };

    load_chunk(0, 0);

    for (int i = 0; i < NC; i++) {
        const int s = i & 1;
        if (i + 1 < NC) { load_chunk(s ^ 1, (i + 1) << 5); cp_wait<1>(); }
        else           { cp_wait<0>(); }
        __syncthreads();

        const uint32_t st = sbase + s * STAGEB;
        #pragma unroll
        for (int kk = 0; kk < 32; kk += 16) {
            uint32_t a_hi[2][4], a_lo[2][4];
            #pragma unroll
            for (int mi = 0; mi < 2; mi++) {
                int row = wm + mi * 16 + a_row_add;
                int col = kk + a_col_add;
                LDMATRIX_X4(a_hi[mi], st + 0 * TILEB + row * ROWB + col * 2);
                LDMATRIX_X4(a_lo[mi], st + 1 * TILEB + row * ROWB + col * 2);
            }
            uint32_t b_hi[4][4], b_lo[4][4];
            #pragma unroll
            for (int nj = 0; nj < 4; nj++) {
                int row = wn + nj * 16 + b_row_add;
                int col = kk + b_col_add;
                LDMATRIX_X4(b_hi[nj], st + 2 * TILEB + row * ROWB + col * 2);
                LDMATRIX_X4(b_lo[nj], st + 3 * TILEB + row * ROWB + col * 2);
            }
            #pragma unroll
            for (int mi = 0; mi < 2; mi++)
                #pragma unroll
                for (int nj = 0; nj < 4; nj++)
                    #pragma unroll
                    for (int h = 0; h < 2; h++) {
                        int ni = nj * 2 + h;
                        MMA_BF16(acc[mi][ni], a_hi[mi], b_hi[nj][h*2], b_hi[nj][h*2+1]);
                        MMA_BF16(acc[mi][ni], a_hi[mi], b_lo[nj][h*2], b_lo[nj][h*2+1]);
                        MMA_BF16(acc[mi][ni], a_lo[mi], b_hi[nj][h*2], b_hi[nj][h*2+1]);
                    }
        }
        __syncthreads();
    }

    // epilogue
    const int g  = lane >> 2;
    const int tg = lane & 3;
    #pragma unroll
    for (int mi = 0; mi < 2; mi++) {
        #pragma unroll
        for (int ni = 0; ni < 8; ni++) {
            int row = m0 + wm + mi * 16 + g;
            int col = n0 + wn + ni * 8 + tg * 2;
            float2 v0 = make_float2(acc[mi][ni][0], acc[mi][ni][1]);
            float2 v1 = make_float2(acc[mi][ni][2], acc[mi][ni][3]);
            *(float2*)(C + (size_t)row * N + col)       = v0;
            *(float2*)(C + (size_t)(row + 8) * N + col) = v1;
        }
    }
}

// ---------------------------------------------------------------------------
// RoPE (unchanged, proven)
// ---------------------------------------------------------------------------
__global__ void rope_kernel(const int* __restrict__ positions)
{
    const int total = Bq * Sq * (NH + NKV) * (HD / 2);
    int idx = blockIdx.x * blockDim.x + threadIdx.x;
    if (idx >= total) return;

    int i  = idx & (HD / 2 - 1);
    int hh = (idx >> 5) % (NH + NKV);
    int bs = idx / ((HD / 2) * (NH + NKV));

    float pos = (float)positions[bs];
    float inv = __expf(-((float)(2 * i) / (float)HD) * 9.210340371976184f);
    float f = pos * inv;
    float c = cosf(f), s = sinf(f);

    float* p = g_qkv + (size_t)bs * QKVW + hh * HD;
    float x1 = p[i];
    float x2 = p[i + HD / 2];
    p[i]          = x1 * c - x2 * s;
    p[i + HD / 2] = x2 * c + x1 * s;
}

// ---------------------------------------------------------------------------
// Causal GQA flash attention (unchanged, proven)
// ---------------------------------------------------------------------------
__global__ __launch_bounds__(64) void attn_kernel()
{
    int qt  = blockIdx.x;
    int h   = blockIdx.y;
    int b   = blockIdx.z;
    int hk  = h / GROUP;
    int tid = threadIdx.x;
    int q_idx = qt * 64 + tid;

    __shared__ float Ks[64 * 64];
    __shared__ float Vs[64 * 64];

    const float* qp = g_qkv + ((size_t)(b * Sq + q_idx)) * QKVW + h * HD;
    float q[HD];
    #pragma unroll
    for (int d = 0; d < HD; d++) q[d] = qp[d] * SCALE;

    float m = -1e30f, l = 0.f;
    float acc[HD];
    #pragma unroll
    for (int d = 0; d < HD; d++) acc[d] = 0.f;

    const size_t kbase = (size_t)b * Sq * QKVW + (size_t)NH * HD + (size_t)hk * HD;
    const size_t vbase = (size_t)b * Sq * QKVW + (size_t)(NH + NKV) * HD + (size_t)hk * HD;

    for (int kb = 0; kb <= qt; kb++) {
        __syncthreads();
        for (int i = tid; i < 64 * 64; i += 64) {
            int j = i >> 6;
            int d = i & 63;
            size_t roff = (size_t)(kb * 64 + j) * QKVW + d;
            Ks[i] = g_qkv[kbase + roff];
            Vs[i] = g_qkv[vbase + roff];
        }
        __syncthreads();

        int jmax = (kb == qt) ? (tid + 1) : 64;
        for (int j = 0; j < jmax; j++) {
            const float* kr = &Ks[j * 64];
            float s = 0.f;
            #pragma unroll
            for (int d = 0; d < HD; d++) s += q[d] * kr[d];

            if (s > m) {
                float corr = __expf(m - s);
                l *= corr;
                #pragma unroll
                for (int d = 0; d < HD; d++) acc[d] *= corr;
                m = s;
            }
            float p = __expf(s - m);
            l += p;
            const float* vr = &Vs[j * 64];
            #pragma unroll
            for (int d = 0; d < HD; d++) acc[d] += p * vr[d];
        }
    }

    float invl = 1.f / l;
    float* op = g_attn + ((size_t)(b * Sq + q_idx)) * (NH * HD) + h * HD;
    #pragma unroll
    for (int d = 0; d < HD; d++) op[d] = acc[d] * invl;
}

// ---------------------------------------------------------------------------
// Launch pipeline
// ---------------------------------------------------------------------------
extern "C" void kernel_launch(void* const* d_in, const int* in_sizes, int n_in,
                              void* d_out, int out_size)
{
    const int*   positions = (const int*)d_in[0];
    const float* hidden    = (const float*)d_in[1];
    const float* Wqkv      = (const float*)d_in[2];
    const float* Wo        = (const float*)d_in[3];
    float*       out       = (float*)d_out;

    float *qkv, *attn;
    cudaGetSymbolAddress((void**)&qkv,  g_qkv);
    cudaGetSymbolAddress((void**)&attn, g_attn);
    __nv_bfloat16 *hid_hi, *hid_lo, *wqkvT_hi, *wqkvT_lo, *woT_hi, *woT_lo, *attn_hi, *attn_lo;
    cudaGetSymbolAddress((void**)&hid_hi,   g_hid_hi);
    cudaGetSymbolAddress((void**)&hid_lo,   g_hid_lo);
    cudaGetSymbolAddress((void**)&wqkvT_hi, g_wqkvT_hi);
    cudaGetSymbolAddress((void**)&wqkvT_lo, g_wqkvT_lo);
    cudaGetSymbolAddress((void**)&woT_hi,   g_woT_hi);
    cudaGetSymbolAddress((void**)&woT_lo,   g_woT_lo);
    cudaGetSymbolAddress((void**)&attn_hi,  g_attn_hi);
    cudaGetSymbolAddress((void**)&attn_lo,  g_attn_lo);

    cudaFuncSetAttribute(gemm_mma,
                         cudaFuncAttributeMaxDynamicSharedMemorySize, GEMM_SMEM);

    // hidden -> bf16 hi/lo
    {
        int n4 = (MROWS * HIDD) / 4;
        convert_split<<<(n4 + 255) / 256, 256>>>(hidden, hid_hi, hid_lo, n4);
    }
    // Wqkv [2048 x 3072] -> bf16 hi/lo [3072 x 2048]
    transpose_split<<<dim3(QKVW / 32, HIDD / 32), dim3(32, 8)>>>(Wqkv, wqkvT_hi, wqkvT_lo, HIDD, QKVW);

    // QKV projection
    gemm_mma<<<dim3(QKVW / 128, MROWS / 128), 256, GEMM_SMEM>>>(
        MROWS, QKVW, HIDD, hid_hi, hid_lo, wqkvT_hi, wqkvT_lo, qkv);

    // RoPE
    {
        int total = Bq * Sq * (NH + NKV) * (HD / 2);
        rope_kernel<<<(total + 255) / 256, 256>>>(positions);
    }

    // Causal GQA attention
    attn_kernel<<<dim3(Sq / 64, NH, Bq), 64>>>();

    // attn fp32 -> bf16 hi/lo
    {
        int n4 = (MROWS * N_HID) / 4;
        convert_split<<<(n4 + 255) / 256, 256>>>(attn, attn_hi, attn_lo, n4);
    }
    // Wo [2048 x 2048] -> bf16 hi/lo transposed
    transpose_split<<<dim3(HIDD / 32, N_HID / 32), dim3(32, 8)>>>(Wo, woT_hi, woT_lo, N_HID, HIDD);

    // Output projection
    gemm_mma<<<dim3(HIDD / 128, MROWS / 128), 256, GEMM_SMEM>>>(
        MROWS, HIDD, N_HID, attn_hi, attn_lo, woT_hi, woT_lo, out);
}

// round 4
// speedup vs baseline: 3.0487x; 2.0693x over previous
#include <cuda_runtime.h>
#include <cuda_bf16.h>
#include <cstdint>
#include <cstddef>

#define Bq   2
#define Sq   2048
#define HIDD 2048
#define NH   32
#define NKV  8
#define HD   64
#define QKVW ((NH + 2 * NKV) * HD)   /* 3072 */
#define GROUP (NH / NKV)             /* 4 */
#define SCALE 0.125f
#define LOG2E 1.4426950408889634f
#define QSCALE (SCALE * LOG2E)

#define MROWS   (Bq * Sq)            /* 4096 */
#define N_HID   (NH * HD)            /* 2048 */

// ---------------------------------------------------------------------------
// Scratch (device globals)
// ---------------------------------------------------------------------------
__device__ float g_qkv [(size_t)Bq * Sq * QKVW];

__device__ __nv_bfloat16 g_hid_hi [(size_t)MROWS * HIDD];
__device__ __nv_bfloat16 g_hid_lo [(size_t)MROWS * HIDD];
__device__ __nv_bfloat16 g_wqkvT_hi[(size_t)QKVW * HIDD];
__device__ __nv_bfloat16 g_wqkvT_lo[(size_t)QKVW * HIDD];
__device__ __nv_bfloat16 g_woT_hi [(size_t)HIDD * N_HID];
__device__ __nv_bfloat16 g_woT_lo [(size_t)HIDD * N_HID];
__device__ __nv_bfloat16 g_attn_hi[(size_t)MROWS * N_HID];
__device__ __nv_bfloat16 g_attn_lo[(size_t)MROWS * N_HID];

// K bf16 hi/lo: [b, hk, kv, d]; V^T bf16 hi/lo: [b, hk, d, kv]
__device__ __nv_bfloat16 g_k_hi [(size_t)Bq * NKV * Sq * HD];
__device__ __nv_bfloat16 g_k_lo [(size_t)Bq * NKV * Sq * HD];
__device__ __nv_bfloat16 g_vt_hi[(size_t)Bq * NKV * HD * Sq];
__device__ __nv_bfloat16 g_vt_lo[(size_t)Bq * NKV * HD * Sq];

// ---------------------------------------------------------------------------
// Helpers
// ---------------------------------------------------------------------------
__device__ __forceinline__ uint32_t smem_u32(const void* p) {
    uint32_t a;
    asm("{ .reg .u64 t; cvta.to.shared.u64 t, %1; cvt.u32.u64 %0, t; }"
        : "=r"(a) : "l"(p));
    return a;
}
__device__ __forceinline__ uint32_t packbf(float x, float y) {   // lo=x, hi=y
    uint32_t r;
    asm("cvt.rn.bf16x2.f32 %0, %1, %2;" : "=r"(r) : "f"(y), "f"(x));
    return r;
}
__device__ __forceinline__ float2 unpackbf(uint32_t v) {
    __nv_bfloat162 t = *reinterpret_cast<__nv_bfloat162*>(&v);
    return make_float2(__bfloat162float(t.x), __bfloat162float(t.y));
}
__device__ __forceinline__ float ex2(float x) {
    float r; asm("ex2.approx.f32 %0, %1;" : "=f"(r) : "f"(x)); return r;
}

#define MMA_BF16(c, a, br0, br1) \
    asm volatile("mma.sync.aligned.m16n8k16.row.col.f32.bf16.bf16.f32 " \
        "{%0,%1,%2,%3}, {%4,%5,%6,%7}, {%8,%9}, {%0,%1,%2,%3};" \
        : "+f"((c)[0]), "+f"((c)[1]), "+f"((c)[2]), "+f"((c)[3]) \
        : "r"((a)[0]), "r"((a)[1]), "r"((a)[2]), "r"((a)[3]), "r"(br0), "r"(br1))

#define LDMATRIX_X4(r, addr) \
    asm volatile("ldmatrix.sync.aligned.m8n8.x4.shared.b16 {%0,%1,%2,%3}, [%4];" \
        : "=r"((r)[0]), "=r"((r)[1]), "=r"((r)[2]), "=r"((r)[3]) : "r"(addr))

#define CP_ASYNC16(saddr, gptr) \
    asm volatile("cp.async.cg.shared.global [%0], [%1], 16;" :: "r"(saddr), "l"(gptr))
#define CP_COMMIT() asm volatile("cp.async.commit_group;" ::: "memory")
template <int N> __device__ __forceinline__ void cp_wait() {
    asm volatile("cp.async.wait_group %0;" :: "n"(N) : "memory");
}

// ---------------------------------------------------------------------------
// fp32 -> bf16 hi/lo split
// ---------------------------------------------------------------------------
__global__ void convert_split(const float* __restrict__ x,
                              __nv_bfloat16* __restrict__ hi,
                              __nv_bfloat16* __restrict__ lo, int n4)
{
    int i = blockIdx.x * blockDim.x + threadIdx.x;
    if (i >= n4) return;
    float4 v = ((const float4*)x)[i];
    uint32_t h01 = packbf(v.x, v.y), h23 = packbf(v.z, v.w);
    float2 f01 = unpackbf(h01), f23 = unpackbf(h23);
    uint32_t l01 = packbf(v.x - f01.x, v.y - f01.y);
    uint32_t l23 = packbf(v.z - f23.x, v.w - f23.y);
    ((uint2*)hi)[i] = make_uint2(h01, h23);
    ((uint2*)lo)[i] = make_uint2(l01, l23);
}

// ---------------------------------------------------------------------------
// Transpose fp32 B[R x C] -> bf16 hi/lo [C x R]
// ---------------------------------------------------------------------------
__global__ void transpose_split(const float* __restrict__ B,
                                __nv_bfloat16* __restrict__ Thi,
                                __nv_bfloat16* __restrict__ Tlo, int R, int C)
{
    __shared__ float t[32][33];
    int x = blockIdx.x * 32 + threadIdx.x;
    int y = blockIdx.y * 32 + threadIdx.y;
    #pragma unroll
    for (int j = 0; j < 32; j += 8)
        t[threadIdx.y + j][threadIdx.x] = B[(size_t)(y + j) * C + x];
    __syncthreads();
    int ox = blockIdx.y * 32 + threadIdx.x;
    int oy = blockIdx.x * 32 + threadIdx.y;
    #pragma unroll
    for (int j = 0; j < 32; j += 8) {
        float v = t[threadIdx.x][threadIdx.y + j];
        __nv_bfloat16 h = __float2bfloat16(v);
        Thi[(size_t)(oy + j) * R + ox] = h;
        Tlo[(size_t)(oy + j) * R + ox] = __float2bfloat16(v - __bfloat162float(h));
    }
}

// ---------------------------------------------------------------------------
// GEMM (R3-proven): C[M,N] = A[M,K] * B^T, 3-product bf16
// ---------------------------------------------------------------------------
#define ROWB       80
#define TILEB      (128 * ROWB)
#define STAGEB     (4 * TILEB)
#define GEMM_SMEM  (2 * STAGEB)

__global__ __launch_bounds__(256, 1) void gemm_mma(
    int M, int N, int K,
    const __nv_bfloat16* __restrict__ Ahi, const __nv_bfloat16* __restrict__ Alo,
    const __nv_bfloat16* __restrict__ Bhi, const __nv_bfloat16* __restrict__ Blo,
    float* __restrict__ C)
{
    extern __shared__ char smem[];
    const uint32_t sbase = smem_u32(smem);
    const int tid  = threadIdx.x;
    const int wid  = tid >> 5;
    const int lane = tid & 31;
    const int m0 = blockIdx.y * 128;
    const int n0 = blockIdx.x * 128;
    const int wm = (wid >> 1) * 32;
    const int wn = (wid & 1) * 64;

    const __nv_bfloat16* srcs[4] = {
        Ahi + (size_t)m0 * K, Alo + (size_t)m0 * K,
        Bhi + (size_t)n0 * K, Blo + (size_t)n0 * K
    };

    const int q  = lane >> 3;
    const int ri = lane & 7;
    const int a_row_add = ((q & 1) << 3) + ri;
    const int a_col_add = (q >> 1) << 3;
    const int b_row_add = ((q >> 1) << 3) + ri;
    const int b_col_add = (q & 1) << 3;

    float acc[2][8][4];
    #pragma unroll
    for (int mi = 0; mi < 2; mi++)
        #pragma unroll
        for (int ni = 0; ni < 8; ni++)
            #pragma unroll
            for (int c = 0; c < 4; c++) acc[mi][ni][c] = 0.f;

    const int NC = K >> 5;

    auto load_chunk = [&](int stage, int k0) {
        uint32_t sdst = sbase + stage * STAGEB;
        #pragma unroll
        for (int t = 0; t < 4; t++) {
            #pragma unroll
            for (int u = 0; u < 2; u++) {
                int idx = tid + u * 256;
                int row = idx >> 2;
                int seg = idx & 3;
                const __nv_bfloat16* g = srcs[t] + (size_t)row * K + k0 + seg * 8;
                CP_ASYNC16(sdst + t * TILEB + row * ROWB + seg * 16, g);
            }
        }
        CP_COMMIT();
    };

    load_chunk(0, 0);

    for (int i = 0; i < NC; i++) {
        const int s = i & 1;
        if (i + 1 < NC) { load_chunk(s ^ 1, (i + 1) << 5); cp_wait<1>(); }
        else           { cp_wait<0>(); }
        __syncthreads();

        const uint32_t st = sbase + s * STAGEB;
        #pragma unroll
        for (int kk = 0; kk < 32; kk += 16) {
            uint32_t a_hi[2][4], a_lo[2][4];
            #pragma unroll
            for (int mi = 0; mi < 2; mi++) {
                int row = wm + mi * 16 + a_row_add;
                int col = kk + a_col_add;
                LDMATRIX_X4(a_hi[mi], st + 0 * TILEB + row * ROWB + col * 2);
                LDMATRIX_X4(a_lo[mi], st + 1 * TILEB + row * ROWB + col * 2);
            }
            uint32_t b_hi[4][4], b_lo[4][4];
            #pragma unroll
            for (int nj = 0; nj < 4; nj++) {
                int row = wn + nj * 16 + b_row_add;
                int col = kk + b_col_add;
                LDMATRIX_X4(b_hi[nj], st + 2 * TILEB + row * ROWB + col * 2);
                LDMATRIX_X4(b_lo[nj], st + 3 * TILEB + row * ROWB + col * 2);
            }
            #pragma unroll
            for (int mi = 0; mi < 2; mi++)
                #pragma unroll
                for (int nj = 0; nj < 4; nj++)
                    #pragma unroll
                    for (int h = 0; h < 2; h++) {
                        int ni = nj * 2 + h;
                        MMA_BF16(acc[mi][ni], a_hi[mi], b_hi[nj][h*2], b_hi[nj][h*2+1]);
                        MMA_BF16(acc[mi][ni], a_hi[mi], b_lo[nj][h*2], b_lo[nj][h*2+1]);
                        MMA_BF16(acc[mi][ni], a_lo[mi], b_hi[nj][h*2], b_hi[nj][h*2+1]);
                    }
        }
        __syncthreads();
    }

    const int g  = lane >> 2;
    const int tg = lane & 3;
    #pragma unroll
    for (int mi = 0; mi < 2; mi++) {
        #pragma unroll
        for (int ni = 0; ni < 8; ni++) {
            int row = m0 + wm + mi * 16 + g;
            int col = n0 + wn + ni * 8 + tg * 2;
            *(float2*)(C + (size_t)row * N + col)       = make_float2(acc[mi][ni][0], acc[mi][ni][1]);
            *(float2*)(C + (size_t)(row + 8) * N + col) = make_float2(acc[mi][ni][2], acc[mi][ni][3]);
        }
    }
}

// ---------------------------------------------------------------------------
// RoPE
// ---------------------------------------------------------------------------
__global__ void rope_kernel(const int* __restrict__ positions)
{
    const int total = Bq * Sq * (NH + NKV) * (HD / 2);
    int idx = blockIdx.x * blockDim.x + threadIdx.x;
    if (idx >= total) return;

    int i  = idx & (HD / 2 - 1);
    int hh = (idx >> 5) % (NH + NKV);
    int bs = idx / ((HD / 2) * (NH + NKV));

    float pos = (float)positions[bs];
    float inv = __expf(-((float)(2 * i) / (float)HD) * 9.210340371976184f);
    float f = pos * inv;
    float c = cosf(f), s = sinf(f);

    float* p = g_qkv + (size_t)bs * QKVW + hh * HD;
    float x1 = p[i];
    float x2 = p[i + HD / 2];
    p[i]          = x1 * c - x2 * s;
    p[i + HD / 2] = x2 * c + x1 * s;
}

// ---------------------------------------------------------------------------
// K/V global bf16 hi/lo conversion; V transposed. grid (32, NKV, Bq), 256 thr
// ---------------------------------------------------------------------------
__global__ __launch_bounds__(256) void convert_kv()
{
    int jt = blockIdx.x, hk = blockIdx.y, b = blockIdx.z;
    int tid = threadIdx.x;
    __shared__ float vt[64][65];

    int r    = tid >> 2;          // 0..63 (kv row within tile)
    int dseg = (tid & 3) * 16;    // 0,16,32,48

    const float* ksrc = g_qkv + (size_t)(b * Sq + jt * 64 + r) * QKVW + NH * HD + hk * HD;
    const float* vsrc = g_qkv + (size_t)(b * Sq + jt * 64 + r) * QKVW + (NH + NKV) * HD + hk * HD;
    __nv_bfloat16* khid = g_k_hi + ((size_t)(b * NKV + hk) * Sq + jt * 64 + r) * HD;
    __nv_bfloat16* klod = g_k_lo + ((size_t)(b * NKV + hk) * Sq + jt * 64 + r) * HD;

    #pragma unroll
    for (int i = 0; i < 4; i++) {
        int d = dseg + i * 4;
        float4 f = *(const float4*)(ksrc + d);
        uint32_t h01 = packbf(f.x, f.y), h23 = packbf(f.z, f.w);
        float2 u01 = unpackbf(h01), u23 = unpackbf(h23);
        uint32_t l01 = packbf(f.x - u01.x, f.y - u01.y);
        uint32_t l23 = packbf(f.z - u23.x, f.w - u23.y);
        *(uint2*)(khid + d) = make_uint2(h01, h23);
        *(uint2*)(klod + d) = make_uint2(l01, l23);

        float4 v = *(const float4*)(vsrc + d);
        vt[r][d + 0] = v.x; vt[r][d + 1] = v.y; vt[r][d + 2] = v.z; vt[r][d + 3] = v.w;
    }
    __syncthreads();

    // transposed write: thread handles d = tid>>2, kv seg = (tid&3)*16
    int d = tid >> 2;
    int kseg = (tid & 3) * 16;
    uint32_t hi8[8], lo8[8];
    #pragma unroll
    for (int i = 0; i < 8; i++) {
        float a = vt[kseg + 2 * i][d];
        float c = vt[kseg + 2 * i + 1][d];
        uint32_t h = packbf(a, c);
        float2 u = unpackbf(h);
        hi8[i] = h;
        lo8[i] = packbf(a - u.x, c - u.y);
    }
    size_t vo = ((size_t)(b * NKV + hk) * HD + d) * Sq + jt * 64 + kseg;
    *(uint4*)(g_vt_hi + vo)     = make_uint4(hi8[0], hi8[1], hi8[2], hi8[3]);
    *(uint4*)(g_vt_hi + vo + 8) = make_uint4(hi8[4], hi8[5], hi8[6], hi8[7]);
    *(uint4*)(g_vt_lo + vo)     = make_uint4(lo8[0], lo8[1], lo8[2], lo8[3]);
    *(uint4*)(g_vt_lo + vo + 8) = make_uint4(lo8[4], lo8[5], lo8[6], lo8[7]);
}

// ---------------------------------------------------------------------------
// mma.sync flash attention. grid (16, NH, Bq), 256 threads (8 warps x m16).
// q-tile 128 rows, kv-tile 64. Writes bf16 hi/lo attention output.
// ---------------------------------------------------------------------------
#define ATT_ROWB   144
#define ATT_TILEB  (64 * ATT_ROWB)    /* 9216 */
#define ATT_STAGEB (4 * ATT_TILEB)    /* 36864: K_hi, K_lo, Vt_hi, Vt_lo */
#define ATT_SMEM   (2 * ATT_STAGEB)   /* 73728 */

__global__ __launch_bounds__(256, 1) void attn_mma()
{
    const int qt = (int)gridDim.x - 1 - (int)blockIdx.x;   // big tiles first
    const int h  = blockIdx.y;
    const int b  = blockIdx.z;
    const int hk = h / GROUP;
    const int q0 = qt * 128;

    extern __shared__ char smem[];
    const uint32_t sb = smem_u32(smem);
    const int tid  = threadIdx.x;
    const int wid  = tid >> 5;
    const int lane = tid & 31;
    const int wm   = wid * 16;
    const int g  = lane >> 2;
    const int tg = lane & 3;
    const int q  = lane >> 3;
    const int ri = lane & 7;
    const int b_row_add = ((q >> 1) << 3) + ri;
    const int b_col_add = (q & 1) << 3;

    // ---- Q fragments (scaled by SCALE*LOG2E, hi/lo split) ----
    uint32_t qa_hi[4][4], qa_lo[4][4];
    {
        const float* qbase = g_qkv + (size_t)(b * Sq + q0 + wm) * QKVW + h * HD;
        #pragma unroll
        for (int kb = 0; kb < 4; kb++) {
            #pragma unroll
            for (int p = 0; p < 4; p++) {
                int row = g + (p & 1) * 8;
                int col = kb * 16 + tg * 2 + (p >> 1) * 8;
                float2 f = *(const float2*)(qbase + (size_t)row * QKVW + col);
                f.x *= QSCALE; f.y *= QSCALE;
                uint32_t hh = packbf(f.x, f.y);
                float2 u = unpackbf(hh);
                qa_hi[kb][p] = hh;
                qa_lo[kb][p] = packbf(f.x - u.x, f.y - u.y);
            }
        }
    }

    float oacc[8][4];
    #pragma unroll
    for (int n = 0; n < 8; n++)
        #pragma unroll
        for (int j = 0; j < 4; j++) oacc[n][j] = 0.f;
    float m0 = -1e30f, m1 = -1e30f, l0 = 0.f, l1 = 0.f;

    const __nv_bfloat16* khi = g_k_hi  + (size_t)(b * NKV + hk) * Sq * HD;
    const __nv_bfloat16* klo = g_k_lo  + (size_t)(b * NKV + hk) * Sq * HD;
    const __nv_bfloat16* vhi = g_vt_hi + (size_t)(b * NKV + hk) * HD * Sq;
    const __nv_bfloat16* vlo = g_vt_lo + (size_t)(b * NKV + hk) * HD * Sq;

    const int ntiles = 2 * qt + 2;

    auto load = [&](int stg, int jt) {
        uint32_t dst = sb + stg * ATT_STAGEB;
        int j0 = jt * 64;
        #pragma unroll
        for (int k = 0; k < 8; k++) {
            int c = tid + k * 256;
            int t = c >> 9;
            int row = (c >> 3) & 63;
            int seg = c & 7;
            const __nv_bfloat16* src;
            if      (t == 0) src = khi + (size_t)(j0 + row) * HD + seg * 8;
            else if (t == 1) src = klo + (size_t)(j0 + row) * HD + seg * 8;
            else if (t == 2) src = vhi + (size_t)row * Sq + j0 + seg * 8;
            else             src = vlo + (size_t)row * Sq + j0 + seg * 8;
            CP_ASYNC16(dst + t * ATT_TILEB + row * ATT_ROWB + seg * 16, src);
        }
        CP_COMMIT();
    };

    load(0, 0);

    for (int t = 0; t < ntiles; t++) {
        const int s = t & 1;
        if (t + 1 < ntiles) { load(s ^ 1, t + 1); cp_wait<1>(); }
        else                { cp_wait<0>(); }
        __syncthreads();

        const int j0 = t * 64;
        if (j0 <= q0 + wm + 15) {   // skip fully-masked warp-tiles
            const uint32_t st = sb + s * ATT_STAGEB;

            // ---- S = Q @ K^T (3-product) ----
            float sc[8][4];
            #pragma unroll
            for (int n = 0; n < 8; n++)
                #pragma unroll
                for (int j = 0; j < 4; j++) sc[n][j] = 0.f;

            #pragma unroll
            for (int kb = 0; kb < 4; kb++) {
                #pragma unroll
                for (int nj = 0; nj < 4; nj++) {
                    uint32_t bh[4], bl[4];
                    uint32_t addr = st + (nj * 16 + b_row_add) * ATT_ROWB + (kb * 16 + b_col_add) * 2;
                    LDMATRIX_X4(bh, addr);
                    LDMATRIX_X4(bl, addr + ATT_TILEB);
                    #pragma unroll
                    for (int hh = 0; hh < 2; hh++) {
                        int n = nj * 2 + hh;
                        MMA_BF16(sc[n], qa_hi[kb], bh[hh*2], bh[hh*2+1]);
                        MMA_BF16(sc[n], qa_hi[kb], bl[hh*2], bl[hh*2+1]);
                        MMA_BF16(sc[n], qa_lo[kb], bh[hh*2], bh[hh*2+1]);
                    }
                }
            }

            // ---- causal mask (diagonal tiles) ----
            if (j0 + 63 > q0 + wm) {
                int r0 = q0 + wm + g;
                #pragma unroll
                for (int n = 0; n < 8; n++) {
                    int cb = j0 + n * 8 + tg * 2;
                    if (cb     > r0)     sc[n][0] = -1e30f;
                    if (cb + 1 > r0)     sc[n][1] = -1e30f;
                    if (cb     > r0 + 8) sc[n][2] = -1e30f;
                    if (cb + 1 > r0 + 8) sc[n][3] = -1e30f;
                }
            }

            // ---- online softmax ----
            float mx0 = -1e30f, mx1 = -1e30f;
            #pragma unroll
            for (int n = 0; n < 8; n++) {
                mx0 = fmaxf(mx0, fmaxf(sc[n][0], sc[n][1]));
                mx1 = fmaxf(mx1, fmaxf(sc[n][2], sc[n][3]));
            }
            mx0 = fmaxf(mx0, __shfl_xor_sync(0xffffffffu, mx0, 1));
            mx0 = fmaxf(mx0, __shfl_xor_sync(0xffffffffu, mx0, 2));
            mx1 = fmaxf(mx1, __shfl_xor_sync(0xffffffffu, mx1, 1));
            mx1 = fmaxf(mx1, __shfl_xor_sync(0xffffffffu, mx1, 2));

            float nm0 = fmaxf(m0, mx0), nm1 = fmaxf(m1, mx1);
            float corr0 = ex2(m0 - nm0), corr1 = ex2(m1 - nm1);
            m0 = nm0; m1 = nm1;

            float s0 = 0.f, s1 = 0.f;
            #pragma unroll
            for (int n = 0; n < 8; n++) {
                sc[n][0] = ex2(sc[n][0] - nm0);
                sc[n][1] = ex2(sc[n][1] - nm0);
                sc[n][2] = ex2(sc[n][2] - nm1);
                sc[n][3] = ex2(sc[n][3] - nm1);
                s0 += sc[n][0] + sc[n][1];
                s1 += sc[n][2] + sc[n][3];
            }
            s0 += __shfl_xor_sync(0xffffffffu, s0, 1);
            s0 += __shfl_xor_sync(0xffffffffu, s0, 2);
            s1 += __shfl_xor_sync(0xffffffffu, s1, 1);
            s1 += __shfl_xor_sync(0xffffffffu, s1, 2);
            l0 = l0 * corr0 + s0;
            l1 = l1 * corr1 + s1;

            #pragma unroll
            for (int n = 0; n < 8; n++) {
                oacc[n][0] *= corr0; oacc[n][1] *= corr0;
                oacc[n][2] *= corr1; oacc[n][3] *= corr1;
            }

            // ---- pack P (hi/lo) as a-frags ----
            uint32_t pa_hi[4][4], pa_lo[4][4];
            #pragma unroll
            for (int kb = 0; kb < 4; kb++) {
                #pragma unroll
                for (int hh = 0; hh < 2; hh++) {
                    int n = 2 * kb + hh;
                    uint32_t h0 = packbf(sc[n][0], sc[n][1]);
                    uint32_t h1 = packbf(sc[n][2], sc[n][3]);
                    float2 u0 = unpackbf(h0), u1 = unpackbf(h1);
                    pa_hi[kb][hh * 2 + 0] = h0;
                    pa_hi[kb][hh * 2 + 1] = h1;
                    pa_lo[kb][hh * 2 + 0] = packbf(sc[n][0] - u0.x, sc[n][1] - u0.y);
                    pa_lo[kb][hh * 2 + 1] = packbf(sc[n][2] - u1.x, sc[n][3] - u1.y);
                }
            }

            // ---- O += P @ V (3-product) ----
            #pragma unroll
            for (int kb = 0; kb < 4; kb++) {
                #pragma unroll
                for (int dg = 0; dg < 4; dg++) {
                    uint32_t vh[4], vl[4];
                    uint32_t addr = st + 2 * ATT_TILEB + (dg * 16 + b_row_add) * ATT_ROWB
                                    + (kb * 16 + b_col_add) * 2;
                    LDMATRIX_X4(vh, addr);
                    LDMATRIX_X4(vl, addr + ATT_TILEB);
                    #pragma unroll
                    for (int hh = 0; hh < 2; hh++) {
                        int n = dg * 2 + hh;
                        MMA_BF16(oacc[n], pa_hi[kb], vh[hh*2], vh[hh*2+1]);
                        MMA_BF16(oacc[n], pa_hi[kb], vl[hh*2], vl[hh*2+1]);
                        MMA_BF16(oacc[n], pa_lo[kb], vh[hh*2], vh[hh*2+1]);
                    }
                }
            }
        }
        __syncthreads();
    }

    // ---- epilogue: normalize, split hi/lo, store ----
    float inv0 = 1.f / l0, inv1 = 1.f / l1;
    int row0 = q0 + wm + g;
    #pragma unroll
    for (int n = 0; n < 8; n++) {
        int col = h * HD + n * 8 + tg * 2;
        size_t o0 = (size_t)(b * Sq + row0) * N_HID + col;
        size_t o1 = (size_t)(b * Sq + row0 + 8) * N_HID + col;
        float a0 = oacc[n][0] * inv0, a1 = oacc[n][1] * inv0;
        float a2 = oacc[n][2] * inv1, a3 = oacc[n][3] * inv1;
        uint32_t h0 = packbf(a0, a1), h1 = packbf(a2, a3);
        float2 u0 = unpackbf(h0), u1 = unpackbf(h1);
        *(uint32_t*)(g_attn_hi + o0) = h0;
        *(uint32_t*)(g_attn_hi + o1) = h1;
        *(uint32_t*)(g_attn_lo + o0) = packbf(a0 - u0.x, a1 - u0.y);
        *(uint32_t*)(g_attn_lo + o1) = packbf(a2 - u1.x, a3 - u1.y);
    }
}

// ---------------------------------------------------------------------------
// Launch pipeline
// ---------------------------------------------------------------------------
extern "C" void kernel_launch(void* const* d_in, const int* in_sizes, int n_in,
                              void* d_out, int out_size)
{
    const int*   positions = (const int*)d_in[0];
    const float* hidden    = (const float*)d_in[1];
    const float* Wqkv      = (const float*)d_in[2];
    const float* Wo        = (const float*)d_in[3];
    float*       out       = (float*)d_out;

    float* qkv;
    cudaGetSymbolAddress((void**)&qkv, g_qkv);
    __nv_bfloat16 *hid_hi, *hid_lo, *wqkvT_hi, *wqkvT_lo, *woT_hi, *woT_lo, *attn_hi, *attn_lo;
    cudaGetSymbolAddress((void**)&hid_hi,   g_hid_hi);
    cudaGetSymbolAddress((void**)&hid_lo,   g_hid_lo);
    cudaGetSymbolAddress((void**)&wqkvT_hi, g_wqkvT_hi);
    cudaGetSymbolAddress((void**)&wqkvT_lo, g_wqkvT_lo);
    cudaGetSymbolAddress((void**)&woT_hi,   g_woT_hi);
    cudaGetSymbolAddress((void**)&woT_lo,   g_woT_lo);
    cudaGetSymbolAddress((void**)&attn_hi,  g_attn_hi);
    cudaGetSymbolAddress((void**)&attn_lo,  g_attn_lo);

    cudaFuncSetAttribute(gemm_mma, cudaFuncAttributeMaxDynamicSharedMemorySize, GEMM_SMEM);
    cudaFuncSetAttribute(attn_mma, cudaFuncAttributeMaxDynamicSharedMemorySize, ATT_SMEM);

    // hidden -> bf16 hi/lo
    {
        int n4 = (MROWS * HIDD) / 4;
        convert_split<<<(n4 + 255) / 256, 256>>>(hidden, hid_hi, hid_lo, n4);
    }
    // Wqkv -> transposed bf16 hi/lo
    transpose_split<<<dim3(QKVW / 32, HIDD / 32), dim3(32, 8)>>>(Wqkv, wqkvT_hi, wqkvT_lo, HIDD, QKVW);

    // QKV projection
    gemm_mma<<<dim3(QKVW / 128, MROWS / 128), 256, GEMM_SMEM>>>(
        MROWS, QKVW, HIDD, hid_hi, hid_lo, wqkvT_hi, wqkvT_lo, qkv);

    // RoPE (q + k)
    {
        int total = Bq * Sq * (NH + NKV) * (HD / 2);
        rope_kernel<<<(total + 255) / 256, 256>>>(positions);
    }

    // K/V -> bf16 hi/lo (V transposed)
    convert_kv<<<dim3(Sq / 64, NKV, Bq), 256>>>();

    // Flash attention (writes g_attn_hi/lo)
    attn_mma<<<dim3(Sq / 128, NH, Bq), 256, ATT_SMEM>>>();

    // Wo -> transposed bf16 hi/lo
    transpose_split<<<dim3(HIDD / 32, N_HID / 32), dim3(32, 8)>>>(Wo, woT_hi, woT_lo, N_HID, HIDD);

    // Output projection
    gemm_mma<<<dim3(HIDD / 128, MROWS / 128), 256, GEMM_SMEM>>>(
        MROWS, HIDD, N_HID, attn_hi, attn_lo, woT_hi, woT_lo, out);
}

// round 5
// speedup vs baseline: 3.4219x; 1.1224x over previous
#include <cuda_runtime.h>
#include <cuda_bf16.h>
#include <cstdint>
#include <cstddef>

#define Bq   2
#define Sq   2048
#define HIDD 2048
#define NH   32
#define NKV  8
#define HD   64
#define QKVW ((NH + 2 * NKV) * HD)   /* 3072 */
#define GROUP (NH / NKV)             /* 4 */
#define SCALE 0.125f
#define LOG2E 1.4426950408889634f
#define QSCALE (SCALE * LOG2E)

#define MROWS   (Bq * Sq)            /* 4096 */
#define N_HID   (NH * HD)            /* 2048 */

// ---------------------------------------------------------------------------
// Scratch (device globals)
// ---------------------------------------------------------------------------
__device__ float g_qkv [(size_t)Bq * Sq * QKVW];

__device__ __nv_bfloat16 g_hid_hi [(size_t)MROWS * HIDD];
__device__ __nv_bfloat16 g_hid_lo [(size_t)MROWS * HIDD];
__device__ __nv_bfloat16 g_wqkvT_hi[(size_t)QKVW * HIDD];
__device__ __nv_bfloat16 g_wqkvT_lo[(size_t)QKVW * HIDD];
__device__ __nv_bfloat16 g_woT_hi [(size_t)HIDD * N_HID];
__device__ __nv_bfloat16 g_woT_lo [(size_t)HIDD * N_HID];
__device__ __nv_bfloat16 g_attn_hi[(size_t)MROWS * N_HID];
__device__ __nv_bfloat16 g_attn_lo[(size_t)MROWS * N_HID];

// K bf16 hi/lo: [b, hk, kv, d]; V^T bf16 hi/lo: [b, hk, d, kv]
__device__ __nv_bfloat16 g_k_hi [(size_t)Bq * NKV * Sq * HD];
__device__ __nv_bfloat16 g_k_lo [(size_t)Bq * NKV * Sq * HD];
__device__ __nv_bfloat16 g_vt_hi[(size_t)Bq * NKV * HD * Sq];
__device__ __nv_bfloat16 g_vt_lo[(size_t)Bq * NKV * HD * Sq];

// ---------------------------------------------------------------------------
// Helpers
// ---------------------------------------------------------------------------
__device__ __forceinline__ uint32_t smem_u32(const void* p) {
    uint32_t a;
    asm("{ .reg .u64 t; cvta.to.shared.u64 t, %1; cvt.u32.u64 %0, t; }"
        : "=r"(a) : "l"(p));
    return a;
}
__device__ __forceinline__ uint32_t packbf(float x, float y) {   // lo=x, hi=y
    uint32_t r;
    asm("cvt.rn.bf16x2.f32 %0, %1, %2;" : "=r"(r) : "f"(y), "f"(x));
    return r;
}
__device__ __forceinline__ float2 unpackbf(uint32_t v) {
    __nv_bfloat162 t = *reinterpret_cast<__nv_bfloat162*>(&v);
    return make_float2(__bfloat162float(t.x), __bfloat162float(t.y));
}
__device__ __forceinline__ float ex2(float x) {
    float r; asm("ex2.approx.f32 %0, %1;" : "=f"(r) : "f"(x)); return r;
}

#define MMA_BF16(c, a, br0, br1) \
    asm volatile("mma.sync.aligned.m16n8k16.row.col.f32.bf16.bf16.f32 " \
        "{%0,%1,%2,%3}, {%4,%5,%6,%7}, {%8,%9}, {%0,%1,%2,%3};" \
        : "+f"((c)[0]), "+f"((c)[1]), "+f"((c)[2]), "+f"((c)[3]) \
        : "r"((a)[0]), "r"((a)[1]), "r"((a)[2]), "r"((a)[3]), "r"(br0), "r"(br1))

#define LDMATRIX_X4(r, addr) \
    asm volatile("ldmatrix.sync.aligned.m8n8.x4.shared.b16 {%0,%1,%2,%3}, [%4];" \
        : "=r"((r)[0]), "=r"((r)[1]), "=r"((r)[2]), "=r"((r)[3]) : "r"(addr))

#define CP_ASYNC16(saddr, gptr) \
    asm volatile("cp.async.cg.shared.global [%0], [%1], 16;" :: "r"(saddr), "l"(gptr))
#define CP_COMMIT() asm volatile("cp.async.commit_group;" ::: "memory")
template <int N> __device__ __forceinline__ void cp_wait() {
    asm volatile("cp.async.wait_group %0;" :: "n"(N) : "memory");
}

// ---------------------------------------------------------------------------
// fp32 -> bf16 hi/lo split
// ---------------------------------------------------------------------------
__global__ void convert_split(const float* __restrict__ x,
                              __nv_bfloat16* __restrict__ hi,
                              __nv_bfloat16* __restrict__ lo, int n4)
{
    int i = blockIdx.x * blockDim.x + threadIdx.x;
    if (i >= n4) return;
    float4 v = ((const float4*)x)[i];
    uint32_t h01 = packbf(v.x, v.y), h23 = packbf(v.z, v.w);
    float2 f01 = unpackbf(h01), f23 = unpackbf(h23);
    uint32_t l01 = packbf(v.x - f01.x, v.y - f01.y);
    uint32_t l23 = packbf(v.z - f23.x, v.w - f23.y);
    ((uint2*)hi)[i] = make_uint2(h01, h23);
    ((uint2*)lo)[i] = make_uint2(l01, l23);
}

// ---------------------------------------------------------------------------
// Transpose fp32 B[R x C] -> bf16 hi/lo [C x R]
// ---------------------------------------------------------------------------
__global__ void transpose_split(const float* __restrict__ B,
                                __nv_bfloat16* __restrict__ Thi,
                                __nv_bfloat16* __restrict__ Tlo, int R, int C)
{
    __shared__ float t[32][33];
    int x = blockIdx.x * 32 + threadIdx.x;
    int y = blockIdx.y * 32 + threadIdx.y;
    #pragma unroll
    for (int j = 0; j < 32; j += 8)
        t[threadIdx.y + j][threadIdx.x] = B[(size_t)(y + j) * C + x];
    __syncthreads();
    int ox = blockIdx.y * 32 + threadIdx.x;
    int oy = blockIdx.x * 32 + threadIdx.y;
    #pragma unroll
    for (int j = 0; j < 32; j += 8) {
        float v = t[threadIdx.x][threadIdx.y + j];
        __nv_bfloat16 h = __float2bfloat16(v);
        Thi[(size_t)(oy + j) * R + ox] = h;
        Tlo[(size_t)(oy + j) * R + ox] = __float2bfloat16(v - __bfloat162float(h));
    }
}

// ---------------------------------------------------------------------------
// GEMM: C[M,N] = A[M,K] * B^T, 3-product bf16; 2 CTAs/SM for latency hiding
// ---------------------------------------------------------------------------
#define ROWB       80
#define TILEB      (128 * ROWB)
#define STAGEB     (4 * TILEB)
#define GEMM_SMEM  (2 * STAGEB)

__global__ __launch_bounds__(256, 2) void gemm_mma(
    int M, int N, int K,
    const __nv_bfloat16* __restrict__ Ahi, const __nv_bfloat16* __restrict__ Alo,
    const __nv_bfloat16* __restrict__ Bhi, const __nv_bfloat16* __restrict__ Blo,
    float* __restrict__ C)
{
    extern __shared__ char smem[];
    const uint32_t sbase = smem_u32(smem);
    const int tid  = threadIdx.x;
    const int wid  = tid >> 5;
    const int lane = tid & 31;
    const int m0 = blockIdx.y * 128;
    const int n0 = blockIdx.x * 128;
    const int wm = (wid >> 1) * 32;
    const int wn = (wid & 1) * 64;

    const __nv_bfloat16* srcs[4] = {
        Ahi + (size_t)m0 * K, Alo + (size_t)m0 * K,
        Bhi + (size_t)n0 * K, Blo + (size_t)n0 * K
    };

    const int q  = lane >> 3;
    const int ri = lane & 7;
    const int a_row_add = ((q & 1) << 3) + ri;
    const int a_col_add = (q >> 1) << 3;
    const int b_row_add = ((q >> 1) << 3) + ri;
    const int b_col_add = (q & 1) << 3;

    float acc[2][8][4];
    #pragma unroll
    for (int mi = 0; mi < 2; mi++)
        #pragma unroll
        for (int ni = 0; ni < 8; ni++)
            #pragma unroll
            for (int c = 0; c < 4; c++) acc[mi][ni][c] = 0.f;

    const int NC = K >> 5;

    auto load_chunk = [&](int stage, int k0) {
        uint32_t sdst = sbase + stage * STAGEB;
        #pragma unroll
        for (int t = 0; t < 4; t++) {
            #pragma unroll
            for (int u = 0; u < 2; u++) {
                int idx = tid + u * 256;
                int row = idx >> 2;
                int seg = idx & 3;
                const __nv_bfloat16* g = srcs[t] + (size_t)row * K + k0 + seg * 8;
                CP_ASYNC16(sdst + t * TILEB + row * ROWB + seg * 16, g);
            }
        }
        CP_COMMIT();
    };

    load_chunk(0, 0);

    for (int i = 0; i < NC; i++) {
        const int s = i & 1;
        if (i + 1 < NC) { load_chunk(s ^ 1, (i + 1) << 5); cp_wait<1>(); }
        else           { cp_wait<0>(); }
        __syncthreads();

        const uint32_t st = sbase + s * STAGEB;
        #pragma unroll
        for (int kk = 0; kk < 32; kk += 16) {
            uint32_t a_hi[2][4], a_lo[2][4];
            #pragma unroll
            for (int mi = 0; mi < 2; mi++) {
                int row = wm + mi * 16 + a_row_add;
                int col = kk + a_col_add;
                LDMATRIX_X4(a_hi[mi], st + 0 * TILEB + row * ROWB + col * 2);
                LDMATRIX_X4(a_lo[mi], st + 1 * TILEB + row * ROWB + col * 2);
            }
            uint32_t b_hi[4][4], b_lo[4][4];
            #pragma unroll
            for (int nj = 0; nj < 4; nj++) {
                int row = wn + nj * 16 + b_row_add;
                int col = kk + b_col_add;
                LDMATRIX_X4(b_hi[nj], st + 2 * TILEB + row * ROWB + col * 2);
                LDMATRIX_X4(b_lo[nj], st + 3 * TILEB + row * ROWB + col * 2);
            }
            #pragma unroll
            for (int mi = 0; mi < 2; mi++)
                #pragma unroll
                for (int nj = 0; nj < 4; nj++)
                    #pragma unroll
                    for (int h = 0; h < 2; h++) {
                        int ni = nj * 2 + h;
                        MMA_BF16(acc[mi][ni], a_hi[mi], b_hi[nj][h*2], b_hi[nj][h*2+1]);
                        MMA_BF16(acc[mi][ni], a_hi[mi], b_lo[nj][h*2], b_lo[nj][h*2+1]);
                        MMA_BF16(acc[mi][ni], a_lo[mi], b_hi[nj][h*2], b_hi[nj][h*2+1]);
                    }
        }
        __syncthreads();
    }

    const int g  = lane >> 2;
    const int tg = lane & 3;
    #pragma unroll
    for (int mi = 0; mi < 2; mi++) {
        #pragma unroll
        for (int ni = 0; ni < 8; ni++) {
            int row = m0 + wm + mi * 16 + g;
            int col = n0 + wn + ni * 8 + tg * 2;
            *(float2*)(C + (size_t)row * N + col)       = make_float2(acc[mi][ni][0], acc[mi][ni][1]);
            *(float2*)(C + (size_t)(row + 8) * N + col) = make_float2(acc[mi][ni][2], acc[mi][ni][3]);
        }
    }
}

// ---------------------------------------------------------------------------
// RoPE
// ---------------------------------------------------------------------------
__global__ void rope_kernel(const int* __restrict__ positions)
{
    const int total = Bq * Sq * (NH + NKV) * (HD / 2);
    int idx = blockIdx.x * blockDim.x + threadIdx.x;
    if (idx >= total) return;

    int i  = idx & (HD / 2 - 1);
    int hh = (idx >> 5) % (NH + NKV);
    int bs = idx / ((HD / 2) * (NH + NKV));

    float pos = (float)positions[bs];
    float inv = __expf(-((float)(2 * i) / (float)HD) * 9.210340371976184f);
    float f = pos * inv;
    float c = cosf(f), s = sinf(f);

    float* p = g_qkv + (size_t)bs * QKVW + hh * HD;
    float x1 = p[i];
    float x2 = p[i + HD / 2];
    p[i]          = x1 * c - x2 * s;
    p[i + HD / 2] = x2 * c + x1 * s;
}

// ---------------------------------------------------------------------------
// K/V global bf16 hi/lo conversion; V transposed. grid (32, NKV, Bq), 256 thr
// ---------------------------------------------------------------------------
__global__ __launch_bounds__(256) void convert_kv()
{
    int jt = blockIdx.x, hk = blockIdx.y, b = blockIdx.z;
    int tid = threadIdx.x;
    __shared__ float vt[64][65];

    int r    = tid >> 2;          // 0..63
    int dseg = (tid & 3) * 16;    // 0,16,32,48

    const float* ksrc = g_qkv + (size_t)(b * Sq + jt * 64 + r) * QKVW + NH * HD + hk * HD;
    const float* vsrc = g_qkv + (size_t)(b * Sq + jt * 64 + r) * QKVW + (NH + NKV) * HD + hk * HD;
    __nv_bfloat16* khid = g_k_hi + ((size_t)(b * NKV + hk) * Sq + jt * 64 + r) * HD;
    __nv_bfloat16* klod = g_k_lo + ((size_t)(b * NKV + hk) * Sq + jt * 64 + r) * HD;

    #pragma unroll
    for (int i = 0; i < 4; i++) {
        int d = dseg + i * 4;
        float4 f = *(const float4*)(ksrc + d);
        uint32_t h01 = packbf(f.x, f.y), h23 = packbf(f.z, f.w);
        float2 u01 = unpackbf(h01), u23 = unpackbf(h23);
        uint32_t l01 = packbf(f.x - u01.x, f.y - u01.y);
        uint32_t l23 = packbf(f.z - u23.x, f.w - u23.y);
        *(uint2*)(khid + d) = make_uint2(h01, h23);
        *(uint2*)(klod + d) = make_uint2(l01, l23);

        float4 v = *(const float4*)(vsrc + d);
        vt[r][d + 0] = v.x; vt[r][d + 1] = v.y; vt[r][d + 2] = v.z; vt[r][d + 3] = v.w;
    }
    __syncthreads();

    int d = tid >> 2;
    int kseg = (tid & 3) * 16;
    uint32_t hi8[8], lo8[8];
    #pragma unroll
    for (int i = 0; i < 8; i++) {
        float a = vt[kseg + 2 * i][d];
        float c = vt[kseg + 2 * i + 1][d];
        uint32_t h = packbf(a, c);
        float2 u = unpackbf(h);
        hi8[i] = h;
        lo8[i] = packbf(a - u.x, c - u.y);
    }
    size_t vo = ((size_t)(b * NKV + hk) * HD + d) * Sq + jt * 64 + kseg;
    *(uint4*)(g_vt_hi + vo)     = make_uint4(hi8[0], hi8[1], hi8[2], hi8[3]);
    *(uint4*)(g_vt_hi + vo + 8) = make_uint4(hi8[4], hi8[5], hi8[6], hi8[7]);
    *(uint4*)(g_vt_lo + vo)     = make_uint4(lo8[0], lo8[1], lo8[2], lo8[3]);
    *(uint4*)(g_vt_lo + vo + 8) = make_uint4(lo8[4], lo8[5], lo8[6], lo8[7]);
}

// ---------------------------------------------------------------------------
// mma.sync flash attention. grid (16, NH, Bq), 256 threads (8 warps x m16).
// q-tile 128, kv-chunk 128 per pipeline stage (two 64-wide halves per sync).
// ---------------------------------------------------------------------------
#define ATT_KROWB  144
#define ATT_KTILE  (128 * ATT_KROWB)   /* 18432 */
#define ATT_VROWB  272
#define ATT_VTILE  (64 * ATT_VROWB)    /* 17408 */
#define ATT_VOFF   (2 * ATT_KTILE)     /* 36864 */
#define ATT_STAGEB (ATT_VOFF + 2 * ATT_VTILE)  /* 71680 */
#define ATT_SMEM   (2 * ATT_STAGEB)    /* 143360 */

__global__ __launch_bounds__(256, 1) void attn_mma()
{
    const int qt = (int)gridDim.x - 1 - (int)blockIdx.x;   // big tiles first
    const int h  = blockIdx.y;
    const int b  = blockIdx.z;
    const int hk = h / GROUP;
    const int q0 = qt * 128;

    extern __shared__ char smem[];
    const uint32_t sb = smem_u32(smem);
    const int tid  = threadIdx.x;
    const int wid  = tid >> 5;
    const int lane = tid & 31;
    const int wm   = wid * 16;
    const int g  = lane >> 2;
    const int tg = lane & 3;
    const int q  = lane >> 3;
    const int ri = lane & 7;
    const int b_row_add = ((q >> 1) << 3) + ri;
    const int b_col_add = (q & 1) << 3;

    // ---- Q fragments (scaled, hi/lo split) ----
    uint32_t qa_hi[4][4], qa_lo[4][4];
    {
        const float* qbase = g_qkv + (size_t)(b * Sq + q0 + wm) * QKVW + h * HD;
        #pragma unroll
        for (int kb = 0; kb < 4; kb++) {
            #pragma unroll
            for (int p = 0; p < 4; p++) {
                int row = g + (p & 1) * 8;
                int col = kb * 16 + tg * 2 + (p >> 1) * 8;
                float2 f = *(const float2*)(qbase + (size_t)row * QKVW + col);
                f.x *= QSCALE; f.y *= QSCALE;
                uint32_t hh = packbf(f.x, f.y);
                float2 u = unpackbf(hh);
                qa_hi[kb][p] = hh;
                qa_lo[kb][p] = packbf(f.x - u.x, f.y - u.y);
            }
        }
    }

    float oacc[8][4];
    #pragma unroll
    for (int n = 0; n < 8; n++)
        #pragma unroll
        for (int j = 0; j < 4; j++) oacc[n][j] = 0.f;
    float m0 = -1e30f, m1 = -1e30f, l0 = 0.f, l1 = 0.f;

    const __nv_bfloat16* khi = g_k_hi  + (size_t)(b * NKV + hk) * Sq * HD;
    const __nv_bfloat16* klo = g_k_lo  + (size_t)(b * NKV + hk) * Sq * HD;
    const __nv_bfloat16* vhi = g_vt_hi + (size_t)(b * NKV + hk) * HD * Sq;
    const __nv_bfloat16* vlo = g_vt_lo + (size_t)(b * NKV + hk) * HD * Sq;

    const int nchunks = qt + 1;   // 128-kv chunks

    auto load = [&](int stg, int ct) {
        uint32_t dst = sb + stg * ATT_STAGEB;
        int j0 = ct * 128;
        #pragma unroll
        for (int k = 0; k < 16; k++) {
            int c = tid + k * 256;
            int t = c >> 10;
            if (t < 2) {
                int row = (c >> 3) & 127;
                int seg = c & 7;
                const __nv_bfloat16* src = (t == 0 ? khi : klo) + (size_t)(j0 + row) * HD + seg * 8;
                CP_ASYNC16(dst + t * ATT_KTILE + row * ATT_KROWB + seg * 16, src);
            } else {
                int row = (c >> 4) & 63;
                int seg = c & 15;
                const __nv_bfloat16* src = (t == 2 ? vhi : vlo) + (size_t)row * Sq + j0 + seg * 8;
                CP_ASYNC16(dst + ATT_VOFF + (t - 2) * ATT_VTILE + row * ATT_VROWB + seg * 16, src);
            }
        }
        CP_COMMIT();
    };

    load(0, 0);

    for (int t = 0; t < nchunks; t++) {
        const int s = t & 1;
        if (t + 1 < nchunks) { load(s ^ 1, t + 1); cp_wait<1>(); }
        else                 { cp_wait<0>(); }
        __syncthreads();

        const uint32_t st = sb + s * ATT_STAGEB;
        #pragma unroll
        for (int half = 0; half < 2; half++) {
            const int j0 = t * 128 + half * 64;
            if (j0 <= q0 + wm + 15) {
                // ---- S = Q @ K^T (3-product) ----
                float sc[8][4];
                #pragma unroll
                for (int n = 0; n < 8; n++)
                    #pragma unroll
                    for (int j = 0; j < 4; j++) sc[n][j] = 0.f;

                #pragma unroll
                for (int kb = 0; kb < 4; kb++) {
                    #pragma unroll
                    for (int nj = 0; nj < 4; nj++) {
                        uint32_t bh[4], bl[4];
                        uint32_t addr = st + (half * 64 + nj * 16 + b_row_add) * ATT_KROWB
                                        + (kb * 16 + b_col_add) * 2;
                        LDMATRIX_X4(bh, addr);
                        LDMATRIX_X4(bl, addr + ATT_KTILE);
                        #pragma unroll
                        for (int hh = 0; hh < 2; hh++) {
                            int n = nj * 2 + hh;
                            MMA_BF16(sc[n], qa_hi[kb], bh[hh*2], bh[hh*2+1]);
                            MMA_BF16(sc[n], qa_hi[kb], bl[hh*2], bl[hh*2+1]);
                            MMA_BF16(sc[n], qa_lo[kb], bh[hh*2], bh[hh*2+1]);
                        }
                    }
                }

                // ---- causal mask (diagonal tiles) ----
                if (j0 + 63 > q0 + wm) {
                    int r0 = q0 + wm + g;
                    #pragma unroll
                    for (int n = 0; n < 8; n++) {
                        int cb = j0 + n * 8 + tg * 2;
                        if (cb     > r0)     sc[n][0] = -1e30f;
                        if (cb + 1 > r0)     sc[n][1] = -1e30f;
                        if (cb     > r0 + 8) sc[n][2] = -1e30f;
                        if (cb + 1 > r0 + 8) sc[n][3] = -1e30f;
                    }
                }

                // ---- online softmax ----
                float mx0 = -1e30f, mx1 = -1e30f;
                #pragma unroll
                for (int n = 0; n < 8; n++) {
                    mx0 = fmaxf(mx0, fmaxf(sc[n][0], sc[n][1]));
                    mx1 = fmaxf(mx1, fmaxf(sc[n][2], sc[n][3]));
                }
                mx0 = fmaxf(mx0, __shfl_xor_sync(0xffffffffu, mx0, 1));
                mx0 = fmaxf(mx0, __shfl_xor_sync(0xffffffffu, mx0, 2));
                mx1 = fmaxf(mx1, __shfl_xor_sync(0xffffffffu, mx1, 1));
                mx1 = fmaxf(mx1, __shfl_xor_sync(0xffffffffu, mx1, 2));

                float nm0 = fmaxf(m0, mx0), nm1 = fmaxf(m1, mx1);
                float corr0 = ex2(m0 - nm0), corr1 = ex2(m1 - nm1);
                m0 = nm0; m1 = nm1;

                float s0 = 0.f, s1 = 0.f;
                #pragma unroll
                for (int n = 0; n < 8; n++) {
                    sc[n][0] = ex2(sc[n][0] - nm0);
                    sc[n][1] = ex2(sc[n][1] - nm0);
                    sc[n][2] = ex2(sc[n][2] - nm1);
                    sc[n][3] = ex2(sc[n][3] - nm1);
                    s0 += sc[n][0] + sc[n][1];
                    s1 += sc[n][2] + sc[n][3];
                }
                s0 += __shfl_xor_sync(0xffffffffu, s0, 1);
                s0 += __shfl_xor_sync(0xffffffffu, s0, 2);
                s1 += __shfl_xor_sync(0xffffffffu, s1, 1);
                s1 += __shfl_xor_sync(0xffffffffu, s1, 2);
                l0 = l0 * corr0 + s0;
                l1 = l1 * corr1 + s1;

                #pragma unroll
                for (int n = 0; n < 8; n++) {
                    oacc[n][0] *= corr0; oacc[n][1] *= corr0;
                    oacc[n][2] *= corr1; oacc[n][3] *= corr1;
                }

                // ---- pack P (hi/lo) as a-frags ----
                uint32_t pa_hi[4][4], pa_lo[4][4];
                #pragma unroll
                for (int kb = 0; kb < 4; kb++) {
                    #pragma unroll
                    for (int hh = 0; hh < 2; hh++) {
                        int n = 2 * kb + hh;
                        uint32_t h0 = packbf(sc[n][0], sc[n][1]);
                        uint32_t h1 = packbf(sc[n][2], sc[n][3]);
                        float2 u0 = unpackbf(h0), u1 = unpackbf(h1);
                        pa_hi[kb][hh * 2 + 0] = h0;
                        pa_hi[kb][hh * 2 + 1] = h1;
                        pa_lo[kb][hh * 2 + 0] = packbf(sc[n][0] - u0.x, sc[n][1] - u0.y);
                        pa_lo[kb][hh * 2 + 1] = packbf(sc[n][2] - u1.x, sc[n][3] - u1.y);
                    }
                }

                // ---- O += P @ V (3-product) ----
                #pragma unroll
                for (int kb = 0; kb < 4; kb++) {
                    #pragma unroll
                    for (int dg = 0; dg < 4; dg++) {
                        uint32_t vh[4], vl[4];
                        uint32_t addr = st + ATT_VOFF + (dg * 16 + b_row_add) * ATT_VROWB
                                        + (half * 64 + kb * 16 + b_col_add) * 2;
                        LDMATRIX_X4(vh, addr);
                        LDMATRIX_X4(vl, addr + ATT_VTILE);
                        #pragma unroll
                        for (int hh = 0; hh < 2; hh++) {
                            int n = dg * 2 + hh;
                            MMA_BF16(oacc[n], pa_hi[kb], vh[hh*2], vh[hh*2+1]);
                            MMA_BF16(oacc[n], pa_hi[kb], vl[hh*2], vl[hh*2+1]);
                            MMA_BF16(oacc[n], pa_lo[kb], vh[hh*2], vh[hh*2+1]);
                        }
                    }
                }
            }
        }
        __syncthreads();
    }

    // ---- epilogue ----
    float inv0 = 1.f / l0, inv1 = 1.f / l1;
    int row0 = q0 + wm + g;
    #pragma unroll
    for (int n = 0; n < 8; n++) {
        int col = h * HD + n * 8 + tg * 2;
        size_t o0 = (size_t)(b * Sq + row0) * N_HID + col;
        size_t o1 = (size_t)(b * Sq + row0 + 8) * N_HID + col;
        float a0 = oacc[n][0] * inv0, a1 = oacc[n][1] * inv0;
        float a2 = oacc[n][2] * inv1, a3 = oacc[n][3] * inv1;
        uint32_t h0 = packbf(a0, a1), h1 = packbf(a2, a3);
        float2 u0 = unpackbf(h0), u1 = unpackbf(h1);
        *(uint32_t*)(g_attn_hi + o0) = h0;
        *(uint32_t*)(g_attn_hi + o1) = h1;
        *(uint32_t*)(g_attn_lo + o0) = packbf(a0 - u0.x, a1 - u0.y);
        *(uint32_t*)(g_attn_lo + o1) = packbf(a2 - u1.x, a3 - u1.y);
    }
}

// ---------------------------------------------------------------------------
// Launch pipeline
// ---------------------------------------------------------------------------
extern "C" void kernel_launch(void* const* d_in, const int* in_sizes, int n_in,
                              void* d_out, int out_size)
{
    const int*   positions = (const int*)d_in[0];
    const float* hidden    = (const float*)d_in[1];
    const float* Wqkv      = (const float*)d_in[2];
    const float* Wo        = (const float*)d_in[3];
    float*       out       = (float*)d_out;

    float* qkv;
    cudaGetSymbolAddress((void**)&qkv, g_qkv);
    __nv_bfloat16 *hid_hi, *hid_lo, *wqkvT_hi, *wqkvT_lo, *woT_hi, *woT_lo, *attn_hi, *attn_lo;
    cudaGetSymbolAddress((void**)&hid_hi,   g_hid_hi);
    cudaGetSymbolAddress((void**)&hid_lo,   g_hid_lo);
    cudaGetSymbolAddress((void**)&wqkvT_hi, g_wqkvT_hi);
    cudaGetSymbolAddress((void**)&wqkvT_lo, g_wqkvT_lo);
    cudaGetSymbolAddress((void**)&woT_hi,   g_woT_hi);
    cudaGetSymbolAddress((void**)&woT_lo,   g_woT_lo);
    cudaGetSymbolAddress((void**)&attn_hi,  g_attn_hi);
    cudaGetSymbolAddress((void**)&attn_lo,  g_attn_lo);

    cudaFuncSetAttribute(gemm_mma, cudaFuncAttributeMaxDynamicSharedMemorySize, GEMM_SMEM);
    cudaFuncSetAttribute(attn_mma, cudaFuncAttributeMaxDynamicSharedMemorySize, ATT_SMEM);

    // hidden -> bf16 hi/lo
    {
        int n4 = (MROWS * HIDD) / 4;
        convert_split<<<(n4 + 255) / 256, 256>>>(hidden, hid_hi, hid_lo, n4);
    }
    // Wqkv -> transposed bf16 hi/lo
    transpose_split<<<dim3(QKVW / 32, HIDD / 32), dim3(32, 8)>>>(Wqkv, wqkvT_hi, wqkvT_lo, HIDD, QKVW);

    // QKV projection
    gemm_mma<<<dim3(QKVW / 128, MROWS / 128), 256, GEMM_SMEM>>>(
        MROWS, QKVW, HIDD, hid_hi, hid_lo, wqkvT_hi, wqkvT_lo, qkv);

    // RoPE (q + k)
    {
        int total = Bq * Sq * (NH + NKV) * (HD / 2);
        rope_kernel<<<(total + 255) / 256, 256>>>(positions);
    }

    // K/V -> bf16 hi/lo (V transposed)
    convert_kv<<<dim3(Sq / 64, NKV, Bq), 256>>>();

    // Flash attention (writes g_attn_hi/lo)
    attn_mma<<<dim3(Sq / 128, NH, Bq), 256, ATT_SMEM>>>();

    // Wo -> transposed bf16 hi/lo
    transpose_split<<<dim3(HIDD / 32, N_HID / 32), dim3(32, 8)>>>(Wo, woT_hi, woT_lo, N_HID, HIDD);

    // Output projection
    gemm_mma<<<dim3(HIDD / 128, MROWS / 128), 256, GEMM_SMEM>>>(
        MROWS, HIDD, N_HID, attn_hi, attn_lo, woT_hi, woT_lo, out);
}